// round 2
// baseline (speedup 1.0000x reference)
#include <cuda_runtime.h>
#include <cstdint>

#define CH  32
#define KNB 27
#define TM  256

__device__ float  g_h1[(size_t)2000128 * CH];
__device__ float  g_part[512 * 64];
__device__ double g_stat[64];
__device__ float  g_bn[64];

__device__ __forceinline__ unsigned long long ffma2(unsigned long long a,
                                                    unsigned long long b,
                                                    unsigned long long c) {
    unsigned long long d;
    asm("fma.rn.f32x2 %0, %1, %2, %3;" : "=l"(d) : "l"(a), "l"(b), "l"(c));
    return d;
}
__device__ __forceinline__ unsigned long long dup2(float x) {
    unsigned long long d;
    asm("mov.b64 %0, {%1, %1};" : "=l"(d) : "f"(x));
    return d;
}
__device__ __forceinline__ float2 unpk(unsigned long long v) {
    float2 r;
    asm("mov.b64 {%0, %1}, %2;" : "=f"(r.x), "=f"(r.y) : "l"(v));
    return r;
}
__device__ __forceinline__ void cpa16(void* dst, const void* src) {
    unsigned sa = (unsigned)__cvta_generic_to_shared(dst);
    asm volatile("cp.async.cg.shared.global [%0], [%1], 16;" :: "r"(sa), "l"(src));
}

// Gathered GEMM: out[n,co] = sum_k sum_ci in[nbr[n,k],ci] * W[k,ci,co]
// 256 threads = 256 points per CTA. Per-thread: 16 packed f32x2 accumulators.
// A tiles double-buffered via cp.async with XOR-chunk swizzle; W[k] double-buffered.
__global__ void __launch_bounds__(256, 2)
conv_kernel(const float* __restrict__ xin, const int* __restrict__ nbr,
            const float* __restrict__ Wg, float* __restrict__ outp, int n)
{
    extern __shared__ float sm[];
    float* A    = sm;                       // 2 * TM * CH floats (64 KB)
    float* sW   = sm + 2 * TM * CH;         // 2 * 1024 floats (8 KB), [ci*32+co]
    int*   idxs = (int*)(sW + 2 * 1024);    // KNB * TM ints (27 KB), [k*TM+r]

    const int t    = threadIdx.x;
    const int base = blockIdx.x * TM;
    const int rows = min(TM, n - base);

    // stage neighbor indices (coalesced read, idxs[k*TM + r])
    for (int i = t; i < TM * KNB; i += 256) {
        int r = i / KNB;
        int v = (r < rows) ? nbr[(size_t)base * KNB + i] : 0;
        int k = i - r * KNB;
        idxs[k * TM + r] = v;
    }
    __syncthreads();

    const int q  = t & 7;     // 16B chunk within a 128B row
    const int rb = t >> 3;    // row group

    // k = 0: gather + weights into buffer 0
    {
        #pragma unroll
        for (int pass = 0; pass < 8; pass++) {
            int r = rb + pass * 32;
            int g = idxs[r];
            cpa16(A + r * CH + ((q ^ (r & 7)) << 2),
                  xin + (size_t)g * CH + (q << 2));
        }
        cpa16(sW + t * 4, Wg + t * 4);
        asm volatile("cp.async.commit_group;" ::: "memory");
    }

    unsigned long long acc[16];
    #pragma unroll
    for (int i = 0; i < 16; i++) acc[i] = 0ull;

    #pragma unroll 1
    for (int k = 0; k < KNB; k++) {
        const int buf = k & 1;
        if (k + 1 < KNB) {
            float* Ad = A + (1 - buf) * TM * CH;
            const int* id = idxs + (k + 1) * TM;
            #pragma unroll
            for (int pass = 0; pass < 8; pass++) {
                int r = rb + pass * 32;
                int g = id[r];
                cpa16(Ad + r * CH + ((q ^ (r & 7)) << 2),
                      xin + (size_t)g * CH + (q << 2));
            }
            cpa16(sW + (1 - buf) * 1024 + t * 4, Wg + (k + 1) * 1024 + t * 4);
            asm volatile("cp.async.commit_group;" ::: "memory");
            asm volatile("cp.async.wait_group 1;" ::: "memory");
        } else {
            asm volatile("cp.async.wait_group 0;" ::: "memory");
        }
        __syncthreads();

        // load my gathered row (logical chunk j at phys chunk j^(t&7)): conflict-free LDS.128
        const float* row = A + buf * TM * CH + t * CH;
        float4 xv[8];
        #pragma unroll
        for (int j = 0; j < 8; j++)
            xv[j] = *(const float4*)(row + ((j ^ (t & 7)) << 2));

        const float* wb = sW + buf * 1024;
        #pragma unroll
        for (int ci = 0; ci < 32; ci++) {
            float xs = ((const float*)xv)[ci];
            unsigned long long xd = dup2(xs);
            const ulonglong2* wr = (const ulonglong2*)(wb + ci * 32);
            #pragma unroll
            for (int jj = 0; jj < 8; jj++) {
                ulonglong2 w = wr[jj];                 // broadcast LDS.128: 2 f32x2 operands
                acc[2 * jj]     = ffma2(xd, w.x, acc[2 * jj]);
                acc[2 * jj + 1] = ffma2(xd, w.y, acc[2 * jj + 1]);
            }
        }
        __syncthreads();
    }

    if (t < rows) {
        float4* orow = (float4*)(outp + (size_t)(base + t) * CH);
        #pragma unroll
        for (int j = 0; j < 8; j++) {
            float2 a = unpk(acc[2 * j]);
            float2 b = unpk(acc[2 * j + 1]);
            orow[j] = make_float4(a.x, a.y, b.x, b.y);
        }
    }
}

// Per-channel sum / sumsq over fixed row slices; deterministic smem tree reduce.
__global__ void stats_kernel(const float* __restrict__ x, int n)
{
    __shared__ float ss[256], sq[256];
    const int t = threadIdx.x;
    const int c = t & 31, rg = t >> 5;
    const int per = (n + 511) / 512;
    int start = blockIdx.x * per;
    int end   = min(start + per, n);
    float s = 0.f, qq = 0.f;
    for (int r = start + rg; r < end; r += 8) {
        float v = x[(size_t)r * 32 + c];
        s += v; qq += v * v;
    }
    ss[t] = s; sq[t] = qq;
    __syncthreads();
    if (t < 128) { ss[t] += ss[t + 128]; sq[t] += sq[t + 128]; }
    __syncthreads();
    if (t < 64)  { ss[t] += ss[t + 64];  sq[t] += sq[t + 64]; }
    __syncthreads();
    if (t < 32) {
        g_part[blockIdx.x * 64 + t]      = ss[t] + ss[t + 32];
        g_part[blockIdx.x * 64 + 32 + t] = sq[t] + sq[t + 32];
    }
}

// Single-CTA fixed-order double reduce -> per-channel scale/shift.
__global__ void reduce_kernel(const float* __restrict__ gamma,
                              const float* __restrict__ beta, int n)
{
    const int t = threadIdx.x;   // 64 threads
    double acc = 0.0;
    #pragma unroll 8
    for (int i = 0; i < 512; i++) acc += (double)g_part[i * 64 + t];
    g_stat[t] = acc;
    __syncthreads();
    if (t < 32) {
        double mean = g_stat[t] / (double)n;
        double var  = g_stat[32 + t] / (double)n - mean * mean;
        float  sc   = (float)((double)gamma[t] / sqrt(var + 1e-4));
        float  sh   = (float)((double)beta[t] - mean * (double)sc);
        g_bn[t] = sc; g_bn[32 + t] = sh;
    }
}

__global__ void bnrelu_kernel(float* __restrict__ x, int n)
{
    int j = blockIdx.x * blockDim.x + threadIdx.x;
    int total  = n * 8;                       // float4s
    int stride = gridDim.x * blockDim.x;      // multiple of 8
    int m = j & 7;
    float4 sc = *(const float4*)(g_bn + m * 4);
    float4 sh = *(const float4*)(g_bn + 32 + m * 4);
    float4* x4 = (float4*)x;
    for (int i = j; i < total; i += stride) {
        float4 v = x4[i];
        v.x = fmaxf(v.x * sc.x + sh.x, 0.f);
        v.y = fmaxf(v.y * sc.y + sh.y, 0.f);
        v.z = fmaxf(v.z * sc.z + sh.z, 0.f);
        v.w = fmaxf(v.w * sc.w + sh.w, 0.f);
        x4[i] = v;
    }
}

__global__ void final_kernel(float* __restrict__ out, const float* __restrict__ feat, int n)
{
    int j = blockIdx.x * blockDim.x + threadIdx.x;
    int total  = n * 8;
    int stride = gridDim.x * blockDim.x;
    int m = j & 7;
    float4 sc = *(const float4*)(g_bn + m * 4);
    float4 sh = *(const float4*)(g_bn + 32 + m * 4);
    float4* o4 = (float4*)out;
    const float4* f4 = (const float4*)feat;
    for (int i = j; i < total; i += stride) {
        float4 v = o4[i];
        float4 f = f4[i];
        v.x = fmaxf(v.x * sc.x + sh.x + f.x, 0.f);
        v.y = fmaxf(v.y * sc.y + sh.y + f.y, 0.f);
        v.z = fmaxf(v.z * sc.z + sh.z + f.z, 0.f);
        v.w = fmaxf(v.w * sc.w + sh.w + f.w, 0.f);
        o4[i] = v;
    }
}

extern "C" void kernel_launch(void* const* d_in, const int* in_sizes, int n_in,
                              void* d_out, int out_size)
{
    const float* feat = (const float*)d_in[0];
    const int*   nbr  = (const int*)  d_in[1];
    const float* W1   = (const float*)d_in[2];
    const float* g1   = (const float*)d_in[3];
    const float* b1   = (const float*)d_in[4];
    const float* W2   = (const float*)d_in[5];
    const float* g2   = (const float*)d_in[6];
    const float* b2   = (const float*)d_in[7];
    int n = in_sizes[0] / CH;
    float* out = (float*)d_out;

    float* h1 = nullptr;
    cudaGetSymbolAddress((void**)&h1, g_h1);

    int smem = (2 * TM * CH + 2 * 1024) * 4 + KNB * TM * 4;   // 101376 B
    cudaFuncSetAttribute(conv_kernel, cudaFuncAttributeMaxDynamicSharedMemorySize, smem);

    int grid = (n + TM - 1) / TM;
    conv_kernel<<<grid, 256, smem>>>(feat, nbr, W1, h1, n);
    stats_kernel<<<512, 256>>>(h1, n);
    reduce_kernel<<<1, 64>>>(g1, b1, n);
    bnrelu_kernel<<<2048, 256>>>(h1, n);
    conv_kernel<<<grid, 256, smem>>>(h1, nbr, W2, out, n);
    stats_kernel<<<512, 256>>>(out, n);
    reduce_kernel<<<1, 64>>>(g2, b2, n);
    final_kernel<<<2048, 256>>>(out, feat, n);
}

// round 3
// speedup vs baseline: 1.3288x; 1.3288x over previous
#include <cuda_runtime.h>
#include <cstdint>

#define CH  32
#define KNB 27
#define TM  256
#define NT  128

__device__ float  g_h1[(size_t)2000128 * CH];
__device__ float  g_part[7816 * 64];
__device__ float  g_bn[64];

__device__ __forceinline__ unsigned long long ffma2(unsigned long long a,
                                                    unsigned long long b,
                                                    unsigned long long c) {
    unsigned long long d;
    asm("fma.rn.f32x2 %0, %1, %2, %3;" : "=l"(d) : "l"(a), "l"(b), "l"(c));
    return d;
}
__device__ __forceinline__ unsigned long long dup2(float x) {
    unsigned long long d;
    asm("mov.b64 %0, {%1, %1};" : "=l"(d) : "f"(x));
    return d;
}
__device__ __forceinline__ float2 unpk(unsigned long long v) {
    float2 r;
    asm("mov.b64 {%0, %1}, %2;" : "=f"(r.x), "=f"(r.y) : "l"(v));
    return r;
}
__device__ __forceinline__ void cpa16(void* dst, const void* src) {
    unsigned sa = (unsigned)__cvta_generic_to_shared(dst);
    asm volatile("cp.async.cg.shared.global [%0], [%1], 16;" :: "r"(sa), "l"(src));
}

// Gathered GEMM + fused per-CTA BN stats.
// out[n,co] = sum_k sum_ci in[nbr[n,k],ci] * W[k,ci,co]
// 128 threads, 2 points/thread (t and t+128). Per ci: 8 broadcast LDS.128 feed
// 32 FFMA2 (1:4 smem:fma). A and W double-buffered via cp.async; A XOR-swizzled.
__global__ void __launch_bounds__(NT, 2)
conv_kernel(const float* __restrict__ xin, const int* __restrict__ nbr,
            const float* __restrict__ Wg, float* __restrict__ outp, int n)
{
    extern __shared__ float sm[];
    float* A    = sm;                       // 2 * TM * CH floats (64 KB)
    float* sW   = sm + 2 * TM * CH;         // 2 * 1024 floats (8 KB), [ci*32+co]
    int*   idxs = (int*)(sW + 2 * 1024);    // KNB * TM ints (27 KB), [k*TM+r]

    const int t    = threadIdx.x;
    const int base = blockIdx.x * TM;
    const int rows = min(TM, n - base);

    for (int i = t; i < TM * KNB; i += NT) {
        int r = i / KNB;
        int v = (r < rows) ? nbr[(size_t)base * KNB + i] : 0;
        int k = i - r * KNB;
        idxs[k * TM + r] = v;
    }
    __syncthreads();

    const int q  = t & 7;     // 16B chunk within 128B row
    const int rb = t >> 3;    // row group (0..15)

    // k = 0 gather + weights -> buffer 0
    {
        #pragma unroll
        for (int p = 0; p < 16; p++) {
            int r = rb + p * 16;
            int g = idxs[r];
            cpa16(A + r * CH + ((q ^ (r & 7)) << 2),
                  xin + (size_t)g * CH + (q << 2));
        }
        cpa16(sW + t * 8,     Wg + t * 8);
        cpa16(sW + t * 8 + 4, Wg + t * 8 + 4);
        asm volatile("cp.async.commit_group;" ::: "memory");
    }

    unsigned long long acc[32];             // [0..15] point t, [16..31] point t+128
    #pragma unroll
    for (int i = 0; i < 32; i++) acc[i] = 0ull;

    #pragma unroll 1
    for (int k = 0; k < KNB; k++) {
        const int buf = k & 1;
        if (k + 1 < KNB) {
            float* Ad = A + (1 - buf) * TM * CH;
            const int* id = idxs + (k + 1) * TM;
            #pragma unroll
            for (int p = 0; p < 16; p++) {
                int r = rb + p * 16;
                int g = id[r];
                cpa16(Ad + r * CH + ((q ^ (r & 7)) << 2),
                      xin + (size_t)g * CH + (q << 2));
            }
            cpa16(sW + (1 - buf) * 1024 + t * 8,     Wg + (k + 1) * 1024 + t * 8);
            cpa16(sW + (1 - buf) * 1024 + t * 8 + 4, Wg + (k + 1) * 1024 + t * 8 + 4);
            asm volatile("cp.async.commit_group;" ::: "memory");
            asm volatile("cp.async.wait_group 1;" ::: "memory");
        } else {
            asm volatile("cp.async.wait_group 0;" ::: "memory");
        }
        __syncthreads();

        const float* r0 = A + buf * TM * CH + t * CH;          // point t
        const float* r1 = r0 + NT * CH;                        // point t+128 (same swizzle key)
        const float* wb = sW + buf * 1024;

        #pragma unroll
        for (int c = 0; c < 8; c++) {
            float4 x0 = *(const float4*)(r0 + ((c ^ (t & 7)) << 2));
            float4 x1 = *(const float4*)(r1 + ((c ^ (t & 7)) << 2));
            #pragma unroll
            for (int u = 0; u < 4; u++) {
                int ci = c * 4 + u;
                unsigned long long xa = dup2(((const float*)&x0)[u]);
                unsigned long long xb = dup2(((const float*)&x1)[u]);
                const ulonglong2* wr = (const ulonglong2*)(wb + ci * 32);
                #pragma unroll
                for (int jj = 0; jj < 8; jj++) {
                    ulonglong2 w = wr[jj];         // broadcast LDS.128
                    acc[2*jj]      = ffma2(xa, w.x, acc[2*jj]);
                    acc[2*jj+1]    = ffma2(xa, w.y, acc[2*jj+1]);
                    acc[16+2*jj]   = ffma2(xb, w.x, acc[16+2*jj]);
                    acc[16+2*jj+1] = ffma2(xb, w.y, acc[16+2*jj+1]);
                }
            }
        }
        __syncthreads();
    }

    const bool v0 = (base + t) < n;
    const bool v1 = (base + t + NT) < n;

    if (v0) {
        float4* o = (float4*)(outp + (size_t)(base + t) * CH);
        #pragma unroll
        for (int jj = 0; jj < 8; jj++) {
            float2 a = unpk(acc[2*jj]);
            float2 b = unpk(acc[2*jj+1]);
            o[jj] = make_float4(a.x, a.y, b.x, b.y);
        }
    }
    if (v1) {
        float4* o = (float4*)(outp + (size_t)(base + t + NT) * CH);
        #pragma unroll
        for (int jj = 0; jj < 8; jj++) {
            float2 a = unpk(acc[16+2*jj]);
            float2 b = unpk(acc[16+2*jj+1]);
            o[jj] = make_float4(a.x, a.y, b.x, b.y);
        }
    }

    // fused BN stats: per-CTA per-channel sum / sumsq (deterministic)
    float* s_sum = A;                 // NT*33 floats (padded)
    float* s_sq  = A + NT * 33;
    #pragma unroll
    for (int jj = 0; jj < 8; jj++) {
        float2 a0 = unpk(acc[2*jj]),    b0 = unpk(acc[2*jj+1]);
        float2 a1 = unpk(acc[16+2*jj]), b1 = unpk(acc[16+2*jj+1]);
        float c0 = v0 ? a0.x : 0.f, c1 = v0 ? a0.y : 0.f;
        float c2 = v0 ? b0.x : 0.f, c3 = v0 ? b0.y : 0.f;
        float d0 = v1 ? a1.x : 0.f, d1 = v1 ? a1.y : 0.f;
        float d2 = v1 ? b1.x : 0.f, d3 = v1 ? b1.y : 0.f;
        s_sum[t*33 + 4*jj+0] = c0 + d0;  s_sq[t*33 + 4*jj+0] = c0*c0 + d0*d0;
        s_sum[t*33 + 4*jj+1] = c1 + d1;  s_sq[t*33 + 4*jj+1] = c1*c1 + d1*d1;
        s_sum[t*33 + 4*jj+2] = c2 + d2;  s_sq[t*33 + 4*jj+2] = c2*c2 + d2*d2;
        s_sum[t*33 + 4*jj+3] = c3 + d3;  s_sq[t*33 + 4*jj+3] = c3*c3 + d3*d3;
    }
    __syncthreads();
    if (t < 32) {
        float s = 0.f, q2 = 0.f;
        for (int i = 0; i < NT; i++) {            // fixed order, conflict-free
            s  += s_sum[i*33 + t];
            q2 += s_sq [i*33 + t];
        }
        g_part[(size_t)blockIdx.x * 64 + t]      = s;
        g_part[(size_t)blockIdx.x * 64 + 32 + t] = q2;
    }
}

// Deterministic final reduce over per-CTA partials -> per-channel scale/shift.
__global__ void reduce_kernel(const float* __restrict__ gamma,
                              const float* __restrict__ beta, int n, int nblk)
{
    __shared__ double sd[512];
    __shared__ double comb[64];
    const int t = threadIdx.x;        // 512
    const int c = t & 63, s = t >> 6; // 8 slices per channel-slot
    double acc = 0.0;
    for (int i = s; i < nblk; i += 8) acc += (double)g_part[(size_t)i * 64 + c];
    sd[t] = acc;
    __syncthreads();
    if (t < 64) {
        double a = 0.0;
        #pragma unroll
        for (int s2 = 0; s2 < 8; s2++) a += sd[t + 64 * s2];
        comb[t] = a;
    }
    __syncthreads();
    if (t < 32) {
        double mean = comb[t] / (double)n;
        double var  = comb[32 + t] / (double)n - mean * mean;
        float  sc   = (float)((double)gamma[t] / sqrt(var + 1e-4));
        float  sh   = (float)((double)beta[t] - mean * (double)sc);
        g_bn[t] = sc; g_bn[32 + t] = sh;
    }
}

__global__ void bnrelu_kernel(float* __restrict__ x, int n)
{
    int j = blockIdx.x * blockDim.x + threadIdx.x;
    int total  = n * 8;
    int stride = gridDim.x * blockDim.x;
    int m = j & 7;
    float4 sc = *(const float4*)(g_bn + m * 4);
    float4 sh = *(const float4*)(g_bn + 32 + m * 4);
    float4* x4 = (float4*)x;
    for (int i = j; i < total; i += stride) {
        float4 v = x4[i];
        v.x = fmaxf(v.x * sc.x + sh.x, 0.f);
        v.y = fmaxf(v.y * sc.y + sh.y, 0.f);
        v.z = fmaxf(v.z * sc.z + sh.z, 0.f);
        v.w = fmaxf(v.w * sc.w + sh.w, 0.f);
        x4[i] = v;
    }
}

__global__ void final_kernel(float* __restrict__ out, const float* __restrict__ feat, int n)
{
    int j = blockIdx.x * blockDim.x + threadIdx.x;
    int total  = n * 8;
    int stride = gridDim.x * blockDim.x;
    int m = j & 7;
    float4 sc = *(const float4*)(g_bn + m * 4);
    float4 sh = *(const float4*)(g_bn + 32 + m * 4);
    float4* o4 = (float4*)out;
    const float4* f4 = (const float4*)feat;
    for (int i = j; i < total; i += stride) {
        float4 v = o4[i];
        float4 f = f4[i];
        v.x = fmaxf(v.x * sc.x + sh.x + f.x, 0.f);
        v.y = fmaxf(v.y * sc.y + sh.y + f.y, 0.f);
        v.z = fmaxf(v.z * sc.z + sh.z + f.z, 0.f);
        v.w = fmaxf(v.w * sc.w + sh.w + f.w, 0.f);
        o4[i] = v;
    }
}

extern "C" void kernel_launch(void* const* d_in, const int* in_sizes, int n_in,
                              void* d_out, int out_size)
{
    const float* feat = (const float*)d_in[0];
    const int*   nbr  = (const int*)  d_in[1];
    const float* W1   = (const float*)d_in[2];
    const float* g1   = (const float*)d_in[3];
    const float* b1   = (const float*)d_in[4];
    const float* W2   = (const float*)d_in[5];
    const float* g2   = (const float*)d_in[6];
    const float* b2   = (const float*)d_in[7];
    int n = in_sizes[0] / CH;
    float* out = (float*)d_out;

    float* h1 = nullptr;
    cudaGetSymbolAddress((void**)&h1, g_h1);

    int smem = (2 * TM * CH + 2 * 1024) * 4 + KNB * TM * 4;   // 101376 B
    cudaFuncSetAttribute(conv_kernel, cudaFuncAttributeMaxDynamicSharedMemorySize, smem);

    int grid = (n + TM - 1) / TM;
    conv_kernel<<<grid, NT, smem>>>(feat, nbr, W1, h1, n);
    reduce_kernel<<<1, 512>>>(g1, b1, n, grid);
    bnrelu_kernel<<<2048, 256>>>(h1, n);
    conv_kernel<<<grid, NT, smem>>>(h1, nbr, W2, out, n);
    reduce_kernel<<<1, 512>>>(g2, b2, n, grid);
    final_kernel<<<2048, 256>>>(out, feat, n);
}